// round 3
// baseline (speedup 1.0000x reference)
#include <cuda_runtime.h>
#include <math.h>

// Problem constants
#define BB 128
#define CC 768
#define NN 196
#define DD 128
#define TK 8
#define NC 16                      // candidate count for exact re-rank
#define M_NODES (BB * NN)          // 25088
#define NE      (M_NODES * TK)     // 200704

// Scratch (device globals; no allocations allowed)
__device__ float  g_nrm[M_NODES * DD];          // normalized nodes (fp32, candidate stage)
__device__ float  g_sim[BB * NN * NN];          // similarity (fp32, candidate stage)
__device__ double g_dinv[M_NODES];              // double 1/||node||
__device__ int    g_cand[M_NODES * NC];         // top-16 fp32 candidates
__device__ int    g_adj[NE];                    // final top-8 indices
__device__ float  g_hidden[(size_t)NE * DD];    // edge-MLP hidden
__device__ float  g_table[27 * 27 * DD];        // pos-MLP table

__device__ __forceinline__ float gelu_exact(float x) {
    return 0.5f * x * (1.0f + erff(x * 0.70710678118654752440f));
}
__device__ __forceinline__ double gelu_exact_d(double x) {
    return 0.5 * x * (1.0 + erf(x * 0.7071067811865475244));
}

// ---------------------------------------------------------------------------
// Kernel 1: pos-MLP table. disp has only 27x27 distinct values (i/13 grid).
// ---------------------------------------------------------------------------
__global__ void pos_table_kernel(const float* __restrict__ Wp1, const float* __restrict__ bp1,
                                 const float* __restrict__ Wp2, const float* __restrict__ bp2) {
    __shared__ float h[64];
    int idx = blockIdx.x;
    float dy = (float)(idx / 27 - 13) * (1.0f / 13.0f);
    float dx = (float)(idx % 27 - 13) * (1.0f / 13.0f);
    int t = threadIdx.x;
    if (t < 64) {
        float v = dy * Wp1[t] + dx * Wp1[64 + t] + bp1[t];
        h[t] = gelu_exact(v);
    }
    __syncthreads();
    float acc = bp2[t];
    #pragma unroll 8
    for (int i = 0; i < 64; i++) acc += h[i] * Wp2[i * DD + t];
    g_table[idx * DD + t] = acc;
}

// ---------------------------------------------------------------------------
// Kernel 2: nodes = GELU(LN(tokens @ W_node + b_node)).
// Chunked-double accumulation: fp32 partials over Kc=16, summed into doubles.
// Tail (LN + GELU) done in double, rounded once to fp32.
// ---------------------------------------------------------------------------
__global__ void node_kernel(const float* __restrict__ feat, const float* __restrict__ Wn,
                            const float* __restrict__ bnode, const float* __restrict__ ln_g,
                            const float* __restrict__ ln_b, float* __restrict__ nodes_out) {
    __shared__ float As[16][65];
    __shared__ float4 Bs[16 * 32];
    __shared__ float Cs[64][128];
    __shared__ int s_base[64];
    int tid = threadIdx.x;
    int m0 = blockIdx.x * 64;
    if (tid < 64) {
        int m = m0 + tid;
        int b = m / NN, n = m % NN;
        s_base[tid] = b * (CC * NN) + n;
    }
    int tx = tid & 31, ty = tid >> 5;
    double dacc[8][4];
    #pragma unroll
    for (int i = 0; i < 8; i++)
        #pragma unroll
        for (int q = 0; q < 4; q++) dacc[i][q] = 0.0;
    __syncthreads();
    for (int k0 = 0; k0 < CC; k0 += 16) {
        #pragma unroll
        for (int i = 0; i < 4; i++) {
            int e = tid + i * 256;
            int r = e & 63, cc = e >> 6;
            As[cc][r] = feat[s_base[r] + (k0 + cc) * NN];
        }
        const float4* Wg = (const float4*)(Wn + k0 * DD);
        Bs[tid] = Wg[tid];
        Bs[tid + 256] = Wg[tid + 256];
        __syncthreads();
        float acc16[8][4];
        #pragma unroll
        for (int i = 0; i < 8; i++)
            #pragma unroll
            for (int q = 0; q < 4; q++) acc16[i][q] = 0.f;
        #pragma unroll
        for (int cc = 0; cc < 16; cc++) {
            float4 bv = Bs[cc * 32 + tx];
            #pragma unroll
            for (int i = 0; i < 8; i++) {
                float a = As[cc][ty + 8 * i];
                acc16[i][0] += a * bv.x; acc16[i][1] += a * bv.y;
                acc16[i][2] += a * bv.z; acc16[i][3] += a * bv.w;
            }
        }
        #pragma unroll
        for (int i = 0; i < 8; i++)
            #pragma unroll
            for (int q = 0; q < 4; q++) dacc[i][q] += (double)acc16[i][q];
        __syncthreads();
    }
    float4 bb = ((const float4*)bnode)[tx];
    #pragma unroll
    for (int i = 0; i < 8; i++) {
        int r = ty + 8 * i;
        // best estimate of the reference's fp32 matmul output: round once
        Cs[r][tx * 4 + 0] = (float)(dacc[i][0] + (double)bb.x);
        Cs[r][tx * 4 + 1] = (float)(dacc[i][1] + (double)bb.y);
        Cs[r][tx * 4 + 2] = (float)(dacc[i][2] + (double)bb.z);
        Cs[r][tx * 4 + 3] = (float)(dacc[i][3] + (double)bb.w);
    }
    __syncthreads();
    // LayerNorm + GELU in double, one warp per row
    int lane = tx, w = ty;
    for (int rr = 0; rr < 8; rr++) {
        int r = w + 8 * rr;
        double x[4];
        double s = 0.0;
        #pragma unroll
        for (int q = 0; q < 4; q++) { x[q] = (double)Cs[r][lane + 32 * q]; s += x[q]; }
        #pragma unroll
        for (int o = 16; o > 0; o >>= 1) s += __shfl_xor_sync(~0u, s, o);
        double mu = s * (1.0 / 128.0);
        double vs = 0.0;
        #pragma unroll
        for (int q = 0; q < 4; q++) { double d = x[q] - mu; vs += d * d; }
        #pragma unroll
        for (int o = 16; o > 0; o >>= 1) vs += __shfl_xor_sync(~0u, vs, o);
        double rs = 1.0 / sqrt(vs * (1.0 / 128.0) + 1e-5);
        int row = m0 + r;
        #pragma unroll
        for (int q = 0; q < 4; q++) {
            int d = lane + 32 * q;
            double y = (x[q] - mu) * rs * (double)ln_g[d] + (double)ln_b[d];
            nodes_out[(size_t)row * DD + d] = (float)gelu_exact_d(y);
        }
    }
}

// ---------------------------------------------------------------------------
// Kernel 3: L2-normalize nodes (warp per row). fp32 normalized copy for the
// candidate-stage sim, double inverse norm for the exact re-rank.
// ---------------------------------------------------------------------------
__global__ void norm_kernel(const float* __restrict__ nodes) {
    int w = (blockIdx.x * blockDim.x + threadIdx.x) >> 5;
    int lane = threadIdx.x & 31;
    if (w >= M_NODES) return;
    const float4* rp = (const float4*)(nodes + (size_t)w * DD);
    float4 v = rp[lane];
    double s = (double)v.x * v.x + (double)v.y * v.y + (double)v.z * v.z + (double)v.w * v.w;
    #pragma unroll
    for (int o = 16; o > 0; o >>= 1) s += __shfl_xor_sync(~0u, s, o);
    double dinv = 1.0 / fmax(sqrt(s), 1e-12);
    if (lane == 0) g_dinv[w] = dinv;
    float inv = (float)dinv;
    ((float4*)(g_nrm + (size_t)w * DD))[lane] =
        make_float4(v.x * inv, v.y * inv, v.z * inv, v.w * inv);
}

// ---------------------------------------------------------------------------
// Kernel 4: sim = nrm @ nrm^T per batch (fp32, candidate stage only).
// ---------------------------------------------------------------------------
__global__ void sim_kernel() {
    int b = blockIdx.z;
    int by = blockIdx.y, bx = blockIdx.x;
    __shared__ float As[128][33];
    __shared__ float Bs2[128][33];
    int tid = threadIdx.x;
    const float* base = g_nrm + (size_t)b * (NN * DD);
    {
        int r = tid >> 3, k0 = (tid & 7) * 16;
        int na = by * 32 + r;
        int ma = bx * 32 + r;
        if (na < NN) {
            const float4* p = (const float4*)(base + na * DD + k0);
            #pragma unroll
            for (int q = 0; q < 4; q++) {
                float4 v = p[q];
                As[k0 + q * 4 + 0][r] = v.x; As[k0 + q * 4 + 1][r] = v.y;
                As[k0 + q * 4 + 2][r] = v.z; As[k0 + q * 4 + 3][r] = v.w;
            }
        } else {
            #pragma unroll
            for (int q = 0; q < 16; q++) As[k0 + q][r] = 0.f;
        }
        if (ma < NN) {
            const float4* p = (const float4*)(base + ma * DD + k0);
            #pragma unroll
            for (int q = 0; q < 4; q++) {
                float4 v = p[q];
                Bs2[k0 + q * 4 + 0][r] = v.x; Bs2[k0 + q * 4 + 1][r] = v.y;
                Bs2[k0 + q * 4 + 2][r] = v.z; Bs2[k0 + q * 4 + 3][r] = v.w;
            }
        } else {
            #pragma unroll
            for (int q = 0; q < 16; q++) Bs2[k0 + q][r] = 0.f;
        }
    }
    __syncthreads();
    int tx = tid & 15, ty = tid >> 4;
    float acc00 = 0.f, acc01 = 0.f, acc10 = 0.f, acc11 = 0.f;
    #pragma unroll 8
    for (int k = 0; k < 128; k++) {
        float a0 = As[k][ty * 2], a1 = As[k][ty * 2 + 1];
        float b0 = Bs2[k][tx * 2], b1 = Bs2[k][tx * 2 + 1];
        acc00 += a0 * b0; acc01 += a0 * b1; acc10 += a1 * b0; acc11 += a1 * b1;
    }
    float* simb = g_sim + (size_t)b * (NN * NN);
    int n0 = by * 32 + ty * 2, m0 = bx * 32 + tx * 2;
    if (n0 < NN) {
        if (m0 < NN)     simb[n0 * NN + m0]     = acc00;
        if (m0 + 1 < NN) simb[n0 * NN + m0 + 1] = acc01;
    }
    if (n0 + 1 < NN) {
        if (m0 < NN)     simb[(n0 + 1) * NN + m0]     = acc10;
        if (m0 + 1 < NN) simb[(n0 + 1) * NN + m0 + 1] = acc11;
    }
}

// ---------------------------------------------------------------------------
// Kernel 5a: fp32 top-16 candidates per row (8-slot safety margin).
// ---------------------------------------------------------------------------
__global__ void cand_kernel() {
    int t = blockIdx.x * blockDim.x + threadIdx.x;
    if (t >= M_NODES) return;
    int b = t / NN, n = t % NN;
    const float* row = g_sim + (size_t)b * (NN * NN) + n * NN;
    float val[NC]; int idx[NC];
    #pragma unroll
    for (int i = 0; i < NC; i++) { val[i] = -1e30f; idx[i] = 0; }
    for (int m = 0; m < NN; m++) {
        if (m == n) continue;
        float v = row[m];
        if (v > val[NC - 1]) {
            int i = NC - 1;
            while (i > 0 && v > val[i - 1]) {
                val[i] = val[i - 1]; idx[i] = idx[i - 1]; i--;
            }
            val[i] = v; idx[i] = m;
        }
    }
    #pragma unroll
    for (int k = 0; k < NC; k++) g_cand[t * NC + k] = idx[k];
}

// ---------------------------------------------------------------------------
// Kernel 5b: exact re-rank. One warp per row: recompute 16 candidate cosines
// in double from fp32 nodes, round to fp32, stable sort (value desc, idx asc)
// to replicate jax.lax.top_k tie semantics. Emit top-8.
// ---------------------------------------------------------------------------
__global__ void refine_kernel(const float* __restrict__ nodes, float* __restrict__ adj_out) {
    __shared__ float skey[8][NC];
    __shared__ int   sidx[8][NC];
    int wip = threadIdx.x >> 5;                 // warp in block
    int lane = threadIdx.x & 31;
    int t = blockIdx.x * 8 + wip;               // row id
    if (t >= M_NODES) return;
    int b = t / NN;
    int rowbase = b * NN;
    double dinv_n = g_dinv[t];
    float4 av = ((const float4*)(nodes + (size_t)t * DD))[lane];
    int myc = (lane < NC) ? g_cand[t * NC + lane] : 0;
    #pragma unroll
    for (int c = 0; c < NC; c++) {
        int j = __shfl_sync(~0u, myc, c);
        float4 bv = ((const float4*)(nodes + (size_t)(rowbase + j) * DD))[lane];
        double p = (double)av.x * bv.x + (double)av.y * bv.y
                 + (double)av.z * bv.z + (double)av.w * bv.w;
        #pragma unroll
        for (int o = 16; o > 0; o >>= 1) p += __shfl_xor_sync(~0u, p, o);
        if (lane == c) {
            double sim = p * dinv_n * g_dinv[rowbase + j];
            skey[wip][c] = (float)sim;
            sidx[wip][c] = j;
        }
    }
    __syncwarp();
    if (lane == 0) {
        float kv[NC]; int ki[NC];
        #pragma unroll
        for (int i = 0; i < NC; i++) { kv[i] = skey[wip][i]; ki[i] = sidx[wip][i]; }
        // insertion sort: descending by value, ascending index on fp32 ties
        #pragma unroll
        for (int i = 1; i < NC; i++) {
            float v = kv[i]; int id = ki[i];
            int p = i - 1;
            while (p >= 0 && (kv[p] < v || (kv[p] == v && ki[p] > id))) {
                kv[p + 1] = kv[p]; ki[p + 1] = ki[p]; p--;
            }
            kv[p + 1] = v; ki[p + 1] = id;
        }
        #pragma unroll
        for (int k = 0; k < TK; k++) {
            g_adj[t * TK + k] = ki[k];
            adj_out[t * TK + k] = (float)ki[k];
        }
    }
}

// ---------------------------------------------------------------------------
// Kernel 6: hidden = GELU([src | nbr | postable] @ We1 + be1).
// ---------------------------------------------------------------------------
__global__ void edge1_kernel(const float* __restrict__ nodes,
                             const float* __restrict__ We1, const float* __restrict__ be1) {
    __shared__ float As[32][65];
    __shared__ float4 Bs[1024];
    __shared__ int s_src[64], s_nbr[64], s_tab[64];
    int tid = threadIdx.x;
    int m0 = blockIdx.x * 64;
    if (tid < 64) {
        int e = m0 + tid;
        int bn = e >> 3;
        int b = bn / NN, n = bn % NN;
        int j = g_adj[e];
        s_src[tid] = (b * NN + n) * DD;
        s_nbr[tid] = (b * NN + j) * DD;
        int rn = n / 14, cn = n % 14, rj = j / 14, cj = j % 14;
        s_tab[tid] = ((rj - rn + 13) * 27 + (cj - cn + 13)) * DD;
    }
    __syncthreads();
    int tx = tid & 31, ty = tid >> 5;
    float acc[8][4] = {};
    for (int k0 = 0; k0 < 384; k0 += 32) {
        int seg = k0 >> 7;
        int off = k0 & 127;
        const float* src = (seg == 2) ? g_table : nodes;
        const int* bases = (seg == 0) ? s_src : (seg == 1) ? s_nbr : s_tab;
        {
            int r = tid >> 2, cb = (tid & 3) * 8;
            const float4* p = (const float4*)(src + bases[r] + off + cb);
            float4 v0 = p[0], v1 = p[1];
            As[cb + 0][r] = v0.x; As[cb + 1][r] = v0.y; As[cb + 2][r] = v0.z; As[cb + 3][r] = v0.w;
            As[cb + 4][r] = v1.x; As[cb + 5][r] = v1.y; As[cb + 6][r] = v1.z; As[cb + 7][r] = v1.w;
        }
        {
            const float4* Wg = (const float4*)(We1 + k0 * DD);
            #pragma unroll
            for (int i = 0; i < 4; i++) Bs[tid + i * 256] = Wg[tid + i * 256];
        }
        __syncthreads();
        #pragma unroll
        for (int cc = 0; cc < 32; cc++) {
            float4 bv = Bs[cc * 32 + tx];
            #pragma unroll
            for (int i = 0; i < 8; i++) {
                float a = As[cc][ty + 8 * i];
                acc[i][0] += a * bv.x; acc[i][1] += a * bv.y;
                acc[i][2] += a * bv.z; acc[i][3] += a * bv.w;
            }
        }
        __syncthreads();
    }
    float4 bb = ((const float4*)be1)[tx];
    #pragma unroll
    for (int i = 0; i < 8; i++) {
        int row = m0 + ty + 8 * i;
        float4 v = make_float4(gelu_exact(acc[i][0] + bb.x), gelu_exact(acc[i][1] + bb.y),
                               gelu_exact(acc[i][2] + bb.z), gelu_exact(acc[i][3] + bb.w));
        ((float4*)(g_hidden + (size_t)row * DD))[tx] = v;
    }
}

// ---------------------------------------------------------------------------
// Kernel 7: edges = hidden @ We2 + be2.
// ---------------------------------------------------------------------------
__global__ void edge2_kernel(const float* __restrict__ We2, const float* __restrict__ be2,
                             float* __restrict__ edges_out) {
    __shared__ float As[32][65];
    __shared__ float4 Bs[1024];
    int tid = threadIdx.x;
    int m0 = blockIdx.x * 64;
    int tx = tid & 31, ty = tid >> 5;
    float acc[8][4] = {};
    for (int k0 = 0; k0 < 128; k0 += 32) {
        {
            int r = tid >> 2, cb = (tid & 3) * 8;
            const float4* p = (const float4*)(g_hidden + (size_t)(m0 + r) * DD + k0 + cb);
            float4 v0 = p[0], v1 = p[1];
            As[cb + 0][r] = v0.x; As[cb + 1][r] = v0.y; As[cb + 2][r] = v0.z; As[cb + 3][r] = v0.w;
            As[cb + 4][r] = v1.x; As[cb + 5][r] = v1.y; As[cb + 6][r] = v1.z; As[cb + 7][r] = v1.w;
        }
        {
            const float4* Wg = (const float4*)(We2 + k0 * DD);
            #pragma unroll
            for (int i = 0; i < 4; i++) Bs[tid + i * 256] = Wg[tid + i * 256];
        }
        __syncthreads();
        #pragma unroll
        for (int cc = 0; cc < 32; cc++) {
            float4 bv = Bs[cc * 32 + tx];
            #pragma unroll
            for (int i = 0; i < 8; i++) {
                float a = As[cc][ty + 8 * i];
                acc[i][0] += a * bv.x; acc[i][1] += a * bv.y;
                acc[i][2] += a * bv.z; acc[i][3] += a * bv.w;
            }
        }
        __syncthreads();
    }
    float4 bb = ((const float4*)be2)[tx];
    #pragma unroll
    for (int i = 0; i < 8; i++) {
        int row = m0 + ty + 8 * i;
        float4 v = make_float4(acc[i][0] + bb.x, acc[i][1] + bb.y,
                               acc[i][2] + bb.z, acc[i][3] + bb.w);
        ((float4*)(edges_out + (size_t)row * DD))[tx] = v;
    }
}

// ---------------------------------------------------------------------------
extern "C" void kernel_launch(void* const* d_in, const int* in_sizes, int n_in,
                              void* d_out, int out_size) {
    const float* feat = (const float*)d_in[0];
    const float* Wn   = (const float*)d_in[1];
    const float* bn   = (const float*)d_in[2];
    const float* lng  = (const float*)d_in[3];
    const float* lnb  = (const float*)d_in[4];
    const float* Wp1  = (const float*)d_in[5];
    const float* bp1  = (const float*)d_in[6];
    const float* Wp2  = (const float*)d_in[7];
    const float* bp2  = (const float*)d_in[8];
    const float* We1  = (const float*)d_in[9];
    const float* be1  = (const float*)d_in[10];
    const float* We2  = (const float*)d_in[11];
    const float* be2  = (const float*)d_in[12];

    float* out = (float*)d_out;
    float* nodes_out = out;                                   // B*N*D
    float* edges_out = out + (size_t)M_NODES * DD;            // B*N*K*D
    float* adj_out   = edges_out + (size_t)NE * DD;           // B*N*K

    pos_table_kernel<<<729, 128>>>(Wp1, bp1, Wp2, bp2);
    node_kernel<<<M_NODES / 64, 256>>>(feat, Wn, bn, lng, lnb, nodes_out);
    norm_kernel<<<(M_NODES * 32) / 256, 256>>>(nodes_out);
    sim_kernel<<<dim3(7, 7, BB), 256>>>();
    cand_kernel<<<(M_NODES + 255) / 256, 256>>>();
    refine_kernel<<<(M_NODES + 7) / 8, 256>>>(nodes_out, adj_out);
    edge1_kernel<<<NE / 64, 256>>>(nodes_out, We1, be1);
    edge2_kernel<<<NE / 64, 256>>>(We2, be2, edges_out);
}